// round 4
// baseline (speedup 1.0000x reference)
#include <cuda_runtime.h>
#include <cuda_fp16.h>

#define NU 100000
#define NV 50000
#define NN 150000
#define DD 64
#define NE 2000000
#define ALPHA (1.0f/3.0f)

#define SCAN_B 256
#define NBLK_SCAN ((NN + SCAN_B - 1) / SCAN_B)   // 586

// ---- device scratch (allocation-free rule: static __device__ globals) ----
__device__ __half g_Eh[NN * DD];   // ego_pos, fp16 (gather table)
__device__ __half g_Ah[NN * DD];   // h1_p, fp16
__device__ __half g_Bh[NN * DD];   // h1_n, fp16
__device__ int    g_cnt_p[NN];
__device__ int    g_cnt_n[NN];
__device__ int    g_off_p[NN];
__device__ int    g_off_n[NN];
__device__ int    g_cur_p[NN];
__device__ int    g_cur_n[NN];
__device__ int    g_src_p[NE];
__device__ int    g_src_n[NE];
__device__ int    g_part_p[1024];
__device__ int    g_part_n[1024];

// ---- K0: build fp16 ego table + zero counters ----
// one thread per half2 element (NN*32 of them)
__global__ void k_init(const float2* __restrict__ ue, const float2* __restrict__ ie) {
    int i = blockIdx.x * blockDim.x + threadIdx.x;
    const int total = NN * 32;
    if (i < total) {
        int n = i >> 5;
        int c = i & 31;
        float2 v = (n < NU) ? ue[n * 32 + c] : ie[(n - NU) * 32 + c];
        reinterpret_cast<__half2*>(g_Eh)[i] = __float22half2_rn(v);
    }
    if (i < NN) { g_cnt_p[i] = 0; g_cnt_n[i] = 0; }
}

// ---- K1: degree histograms (2 edges/thread) ----
__global__ void k_hist(const int* __restrict__ pd, const int* __restrict__ nd) {
    int e = (blockIdx.x * blockDim.x + threadIdx.x) * 2;
    if (e < NE) {
        int2 d1 = __ldcs(reinterpret_cast<const int2*>(pd + e));
        atomicAdd(&g_cnt_p[d1.x], 1);
        atomicAdd(&g_cnt_p[d1.y], 1);
        int2 d2 = __ldcs(reinterpret_cast<const int2*>(nd + e));
        atomicAdd(&g_cnt_n[d2.x], 1);
        atomicAdd(&g_cnt_n[d2.y], 1);
    }
}

// ---- K2a: per-block exclusive scan of counts ----
__global__ void k_scan1() {
    __shared__ int s[SCAN_B];
    int list = blockIdx.y;
    const int* cnt = list ? g_cnt_n : g_cnt_p;
    int* off       = list ? g_off_n : g_off_p;
    int* part      = list ? g_part_n : g_part_p;

    int gid = blockIdx.x * SCAN_B + threadIdx.x;
    int v = (gid < NN) ? cnt[gid] : 0;
    int x = v;
    s[threadIdx.x] = x;
    __syncthreads();
    for (int o = 1; o < SCAN_B; o <<= 1) {
        int t = (threadIdx.x >= o) ? s[threadIdx.x - o] : 0;
        __syncthreads();
        x += t;
        s[threadIdx.x] = x;
        __syncthreads();
    }
    if (gid < NN) off[gid] = x - v;
    if (threadIdx.x == SCAN_B - 1) part[blockIdx.x] = x;
}

// ---- K2b: parallel exclusive scan of block partials ----
__global__ void k_scan2() {
    __shared__ int s[1024];
    int* part = blockIdx.x ? g_part_n : g_part_p;
    int t = threadIdx.x;
    int v = (t < NBLK_SCAN) ? part[t] : 0;
    int x = v;
    s[t] = x;
    __syncthreads();
    for (int o = 1; o < 1024; o <<= 1) {
        int tt = (t >= o) ? s[t - o] : 0;
        __syncthreads();
        x += tt;
        s[t] = x;
        __syncthreads();
    }
    if (t < NBLK_SCAN) part[t] = x - v;
}

// ---- K2c: finalize offsets; init fill cursors ----
__global__ void k_scan3() {
    int gid = blockIdx.x * SCAN_B + threadIdx.x;
    if (gid >= NN) return;
    if (blockIdx.y == 0) {
        int o = g_off_p[gid] + g_part_p[gid >> 8];
        g_off_p[gid] = o; g_cur_p[gid] = o;
    } else {
        int o = g_off_n[gid] + g_part_n[gid >> 8];
        g_off_n[gid] = o; g_cur_n[gid] = o;
    }
}

// ---- K3: counting-sort fill (2 edges/thread) ----
__global__ void k_fill(const int* __restrict__ ps, const int* __restrict__ pd,
                       const int* __restrict__ ns, const int* __restrict__ nd) {
    int e = (blockIdx.x * blockDim.x + threadIdx.x) * 2;
    if (e < NE) {
        int2 s1 = __ldcs(reinterpret_cast<const int2*>(ps + e));
        int2 d1 = __ldcs(reinterpret_cast<const int2*>(pd + e));
        g_src_p[atomicAdd(&g_cur_p[d1.x], 1)] = s1.x;
        g_src_p[atomicAdd(&g_cur_p[d1.y], 1)] = s1.y;
        int2 s2 = __ldcs(reinterpret_cast<const int2*>(ns + e));
        int2 d2 = __ldcs(reinterpret_cast<const int2*>(nd + e));
        g_src_n[atomicAdd(&g_cur_n[d2.x], 1)] = s2.x;
        g_src_n[atomicAdd(&g_cur_n[d2.y], 1)] = s2.y;
    }
}

// ---- gather: fp16 rows, fp32 dual accumulators ----
__device__ __forceinline__ void gather_accum_h(const __half2* __restrict__ X,
                                               const int* __restrict__ srclist,
                                               int start, int cnt, int lane,
                                               float2& acc0, float2& acc1) {
    for (int base = 0; base < cnt; base += 32) {
        int rem = cnt - base;
        int m = rem < 32 ? rem : 32;
        int idx = (lane < m) ? __ldcs(&srclist[start + base + lane]) : 0;
        int kfull = m & ~1;
        #pragma unroll 4
        for (int k = 0; k < kfull; k += 2) {
            int j0 = __shfl_sync(0xffffffffu, idx, k);
            int j1 = __shfl_sync(0xffffffffu, idx, k + 1);
            float2 v0 = __half22float2(X[j0 * 32 + lane]);
            float2 v1 = __half22float2(X[j1 * 32 + lane]);
            acc0.x += v0.x; acc0.y += v0.y;
            acc1.x += v1.x; acc1.y += v1.y;
        }
        if (m & 1) {
            int j = __shfl_sync(0xffffffffu, idx, m - 1);
            float2 v = __half22float2(X[j * 32 + lane]);
            acc0.x += v.x; acc0.y += v.y;
        }
    }
}

// ---- K4: layer 1 fused (pos+neg conv, acc init, self-terms fp32) ----
__global__ void __launch_bounds__(256) k_conv1(const float* __restrict__ ue,
                                               const float* __restrict__ ie,
                                               const float* __restrict__ un,
                                               const float* __restrict__ inn,
                                               float* __restrict__ out) {
    int warp = (blockIdx.x * blockDim.x + threadIdx.x) >> 5;
    int lane = threadIdx.x & 31;
    if (warp >= NN) return;
    int node = warp;

    const __half2* E = reinterpret_cast<const __half2*>(g_Eh);

    float2 ap0 = make_float2(0.f, 0.f), ap1 = make_float2(0.f, 0.f);
    float2 an0 = make_float2(0.f, 0.f), an1 = make_float2(0.f, 0.f);
    gather_accum_h(E, g_src_p, g_off_p[node], g_cnt_p[node], lane, ap0, ap1);
    gather_accum_h(E, g_src_n, g_off_n[node], g_cnt_n[node], lane, an0, an1);

    // fp32 self-terms straight from inputs (exact)
    float2 ego = (node < NU)
        ? reinterpret_cast<const float2*>(ue)[node * 32 + lane]
        : reinterpret_cast<const float2*>(ie)[(node - NU) * 32 + lane];
    float2 egon = (node < NU)
        ? reinterpret_cast<const float2*>(un)[node * 32 + lane]
        : reinterpret_cast<const float2*>(inn)[(node - NU) * 32 + lane];

    float2 h1p, h1n;
    h1p.x = ego.x + ap0.x + ap1.x;  h1p.y = ego.y + ap0.y + ap1.y;
    h1n.x = ego.x + an0.x + an1.x;  h1n.y = ego.y + an0.y + an1.y;

    reinterpret_cast<__half2*>(g_Ah)[node * 32 + lane] = __float22half2_rn(h1p);
    reinterpret_cast<__half2*>(g_Bh)[node * 32 + lane] = __float22half2_rn(h1n);

    float2 op, on;
    op.x = ALPHA * (ego.x + h1p.x);  op.y = ALPHA * (ego.y + h1p.y);
    on.x = ALPHA * (egon.x + h1n.x); on.y = ALPHA * (egon.y + h1n.y);
    __stwt(reinterpret_cast<float2*>(out) + node * 32 + lane, op);
    __stwt(reinterpret_cast<float2*>(out + (size_t)NN * DD) + node * 32 + lane, on);
}

// ---- K5: layer 2 fused (gather h1 fp16, final acc) ----
__global__ void __launch_bounds__(256) k_conv2(float* __restrict__ out) {
    int warp = (blockIdx.x * blockDim.x + threadIdx.x) >> 5;
    int lane = threadIdx.x & 31;
    if (warp >= NN) return;
    int node = warp;

    const __half2* A = reinterpret_cast<const __half2*>(g_Ah);
    const __half2* B = reinterpret_cast<const __half2*>(g_Bh);

    // self terms (fp16-quantized h1, error negligible in the alpha-sum)
    float2 ap0 = __half22float2(A[node * 32 + lane]);
    float2 an0 = __half22float2(B[node * 32 + lane]);
    float2 ap1 = make_float2(0.f, 0.f), an1 = make_float2(0.f, 0.f);

    gather_accum_h(A, g_src_p, g_off_p[node], g_cnt_p[node], lane, ap0, ap1);
    gather_accum_h(B, g_src_n, g_off_n[node], g_cnt_n[node], lane, an0, an1);

    float2* outp = reinterpret_cast<float2*>(out);
    float2* outn = reinterpret_cast<float2*>(out + (size_t)NN * DD);
    float2 pp = __ldcs(outp + node * 32 + lane);
    float2 pn = __ldcs(outn + node * 32 + lane);
    pp.x += ALPHA * (ap0.x + ap1.x);  pp.y += ALPHA * (ap0.y + ap1.y);
    pn.x += ALPHA * (an0.x + an1.x);  pn.y += ALPHA * (an0.y + an1.y);
    __stwt(outp + node * 32 + lane, pp);
    __stwt(outn + node * 32 + lane, pn);
}

extern "C" void kernel_launch(void* const* d_in, const int* in_sizes, int n_in,
                              void* d_out, int out_size) {
    const float* ue  = (const float*)d_in[0];
    const float* ie  = (const float*)d_in[1];
    const float* un  = (const float*)d_in[2];
    const float* inn = (const float*)d_in[3];
    const int* pe    = (const int*)d_in[4];
    const int* ne    = (const int*)d_in[5];
    float* out = (float*)d_out;

    const int* ps = pe;        const int* pd = pe + NE;
    const int* ns = ne;        const int* nd = ne + NE;

    {
        int total = NN * 32;   // half2 elements
        int blk = (total + 255) / 256;
        k_init<<<blk, 256>>>((const float2*)ue, (const float2*)ie);
    }
    k_hist<<<(NE / 2 + 255) / 256, 256>>>(pd, nd);
    {
        dim3 g1(NBLK_SCAN, 2);
        k_scan1<<<g1, SCAN_B>>>();
        k_scan2<<<2, 1024>>>();
        k_scan3<<<g1, SCAN_B>>>();
    }
    k_fill<<<(NE / 2 + 255) / 256, 256>>>(ps, pd, ns, nd);

    int conv_blocks = NN / 8;   // warp per node, 8 warps/block
    k_conv1<<<conv_blocks, 256>>>(ue, ie, un, inn, out);
    k_conv2<<<conv_blocks, 256>>>(out);
}

// round 5
// speedup vs baseline: 1.1318x; 1.1318x over previous
#include <cuda_runtime.h>

#define NU 100000
#define NV 50000
#define NN 150000
#define DD 64
#define NE 2000000
#define ALPHA (1.0f/3.0f)
#define FULLM 0xffffffffu

#define SCAN_B 256
#define NBLK_SCAN ((NN + SCAN_B - 1) / SCAN_B)   // 586

// ---- device scratch ----
__device__ float g_A[NN * DD];     // h1_p
__device__ float g_B[NN * DD];     // h1_n
__device__ int   g_cnt_p[NN];
__device__ int   g_cnt_n[NN];
__device__ int2  g_meta_p[NN];     // (off, cnt)
__device__ int2  g_meta_n[NN];
__device__ int   g_off_p[NN];
__device__ int   g_off_n[NN];
__device__ int   g_cur_p[NN];
__device__ int   g_cur_n[NN];
__device__ int   g_src_p[NE];
__device__ int   g_src_n[NE];
__device__ int   g_part_p[1024];
__device__ int   g_part_n[1024];

// ---- K0: zero counters ----
__global__ void k_zero() {
    int i = blockIdx.x * blockDim.x + threadIdx.x;
    if (i < NN) { g_cnt_p[i] = 0; g_cnt_n[i] = 0; }
}

// ---- K1: degree histograms (2 edges/thread) ----
__global__ void k_hist(const int* __restrict__ pd, const int* __restrict__ nd) {
    int e = (blockIdx.x * blockDim.x + threadIdx.x) * 2;
    if (e < NE) {
        int2 d1 = __ldcs(reinterpret_cast<const int2*>(pd + e));
        atomicAdd(&g_cnt_p[d1.x], 1);
        atomicAdd(&g_cnt_p[d1.y], 1);
        int2 d2 = __ldcs(reinterpret_cast<const int2*>(nd + e));
        atomicAdd(&g_cnt_n[d2.x], 1);
        atomicAdd(&g_cnt_n[d2.y], 1);
    }
}

// ---- K2a: per-block exclusive scan of counts ----
__global__ void k_scan1() {
    __shared__ int s[SCAN_B];
    int list = blockIdx.y;
    const int* cnt = list ? g_cnt_n : g_cnt_p;
    int* off       = list ? g_off_n : g_off_p;
    int* part      = list ? g_part_n : g_part_p;

    int gid = blockIdx.x * SCAN_B + threadIdx.x;
    int v = (gid < NN) ? cnt[gid] : 0;
    int x = v;
    s[threadIdx.x] = x;
    __syncthreads();
    for (int o = 1; o < SCAN_B; o <<= 1) {
        int t = (threadIdx.x >= o) ? s[threadIdx.x - o] : 0;
        __syncthreads();
        x += t;
        s[threadIdx.x] = x;
        __syncthreads();
    }
    if (gid < NN) off[gid] = x - v;
    if (threadIdx.x == SCAN_B - 1) part[blockIdx.x] = x;
}

// ---- K2b: parallel exclusive scan of block partials ----
__global__ void k_scan2() {
    __shared__ int s[1024];
    int* part = blockIdx.x ? g_part_n : g_part_p;
    int t = threadIdx.x;
    int v = (t < NBLK_SCAN) ? part[t] : 0;
    int x = v;
    s[t] = x;
    __syncthreads();
    for (int o = 1; o < 1024; o <<= 1) {
        int tt = (t >= o) ? s[t - o] : 0;
        __syncthreads();
        x += tt;
        s[t] = x;
        __syncthreads();
    }
    if (t < NBLK_SCAN) part[t] = x - v;
}

// ---- K2c: finalize offsets; write meta; init cursors ----
__global__ void k_scan3() {
    int gid = blockIdx.x * SCAN_B + threadIdx.x;
    if (gid >= NN) return;
    if (blockIdx.y == 0) {
        int o = g_off_p[gid] + g_part_p[gid >> 8];
        g_meta_p[gid] = make_int2(o, g_cnt_p[gid]);
        g_cur_p[gid] = o;
    } else {
        int o = g_off_n[gid] + g_part_n[gid >> 8];
        g_meta_n[gid] = make_int2(o, g_cnt_n[gid]);
        g_cur_n[gid] = o;
    }
}

// ---- K3: counting-sort fill (2 edges/thread) ----
__global__ void k_fill(const int* __restrict__ ps, const int* __restrict__ pd,
                       const int* __restrict__ ns, const int* __restrict__ nd) {
    int e = (blockIdx.x * blockDim.x + threadIdx.x) * 2;
    if (e < NE) {
        int2 s1 = __ldcs(reinterpret_cast<const int2*>(ps + e));
        int2 d1 = __ldcs(reinterpret_cast<const int2*>(pd + e));
        g_src_p[atomicAdd(&g_cur_p[d1.x], 1)] = s1.x;
        g_src_p[atomicAdd(&g_cur_p[d1.y], 1)] = s1.y;
        int2 s2 = __ldcs(reinterpret_cast<const int2*>(ns + e));
        int2 d2 = __ldcs(reinterpret_cast<const int2*>(nd + e));
        g_src_n[atomicAdd(&g_cur_n[d2.x], 1)] = s2.x;
        g_src_n[atomicAdd(&g_cur_n[d2.y], 1)] = s2.y;
    }
}

// ---- gather sources ----
struct SrcEgo {
    const float2* ue; const float2* ie;
    __device__ __forceinline__ float2 operator()(int j, int lane) const {
        return (j < NU) ? ue[j * 32 + lane] : ie[(j - NU) * 32 + lane];
    }
};
struct SrcTab {
    const float2* t;
    __device__ __forceinline__ float2 operator()(int j, int lane) const {
        return t[j * 32 + lane];
    }
};

// ---- gather: R1-style inner loop (unroll 4, independent loads), preloaded
//      first idx chunk to cut the serial prologue ----
template <class LD>
__device__ __forceinline__ void gather_accum(LD ld, const int* __restrict__ srclist,
                                             int start, int cnt, int lane,
                                             int idx, float2& acc) {
    if (cnt <= 0) return;
    int base = 0;
    while (true) {
        int m = cnt - base; if (m > 32) m = 32;
        #pragma unroll 4
        for (int k = 0; k < m; k++) {
            int j = __shfl_sync(FULLM, idx, k);
            float2 v = ld(j, lane);
            acc.x += v.x;
            acc.y += v.y;
        }
        base += 32;
        if (base >= cnt) break;
        int mm = cnt - base; if (mm > 32) mm = 32;
        idx = (lane < mm) ? srclist[start + base + lane] : 0;
    }
}

// ---- K4: layer 1 fused ----
__global__ void __launch_bounds__(256) k_conv1(const float* __restrict__ ue,
                                               const float* __restrict__ ie,
                                               const float* __restrict__ un,
                                               const float* __restrict__ inn,
                                               float* __restrict__ out) {
    int warp = (blockIdx.x * blockDim.x + threadIdx.x) >> 5;
    int lane = threadIdx.x & 31;
    if (warp >= NN) return;
    int node = warp;

    // overlapped prologue: meta + both first idx chunks + self terms
    int2 mp = g_meta_p[node];
    int2 mn = g_meta_n[node];
    int m0p = mp.y < 32 ? mp.y : 32;
    int m0n = mn.y < 32 ? mn.y : 32;
    int idxp = (lane < m0p) ? g_src_p[mp.x + lane] : 0;
    int idxn = (lane < m0n) ? g_src_n[mn.x + lane] : 0;

    const float2* ue2 = reinterpret_cast<const float2*>(ue);
    const float2* ie2 = reinterpret_cast<const float2*>(ie);
    float2 ego = (node < NU) ? ue2[node * 32 + lane]
                             : ie2[(node - NU) * 32 + lane];
    float2 egon = (node < NU)
        ? reinterpret_cast<const float2*>(un)[node * 32 + lane]
        : reinterpret_cast<const float2*>(inn)[(node - NU) * 32 + lane];

    SrcEgo ld{ue2, ie2};
    float2 ap = ego, an = ego;   // self term (eps=0 GIN)
    gather_accum(ld, g_src_p, mp.x, mp.y, lane, idxp, ap);
    gather_accum(ld, g_src_n, mn.x, mn.y, lane, idxn, an);

    reinterpret_cast<float2*>(g_A)[node * 32 + lane] = ap;
    reinterpret_cast<float2*>(g_B)[node * 32 + lane] = an;

    float2 op, on;
    op.x = ALPHA * (ego.x + ap.x);  op.y = ALPHA * (ego.y + ap.y);
    on.x = ALPHA * (egon.x + an.x); on.y = ALPHA * (egon.y + an.y);
    reinterpret_cast<float2*>(out)[node * 32 + lane] = op;
    reinterpret_cast<float2*>(out + (size_t)NN * DD)[node * 32 + lane] = on;
}

// ---- K5: layer 2 fused ----
__global__ void __launch_bounds__(256) k_conv2(float* __restrict__ out) {
    int warp = (blockIdx.x * blockDim.x + threadIdx.x) >> 5;
    int lane = threadIdx.x & 31;
    if (warp >= NN) return;
    int node = warp;

    int2 mp = g_meta_p[node];
    int2 mn = g_meta_n[node];
    int m0p = mp.y < 32 ? mp.y : 32;
    int m0n = mn.y < 32 ? mn.y : 32;
    int idxp = (lane < m0p) ? g_src_p[mp.x + lane] : 0;
    int idxn = (lane < m0n) ? g_src_n[mn.x + lane] : 0;

    const float2* A2 = reinterpret_cast<const float2*>(g_A);
    const float2* B2 = reinterpret_cast<const float2*>(g_B);

    float2 ap = A2[node * 32 + lane];   // self term
    float2 an = B2[node * 32 + lane];
    gather_accum(SrcTab{A2}, g_src_p, mp.x, mp.y, lane, idxp, ap);
    gather_accum(SrcTab{B2}, g_src_n, mn.x, mn.y, lane, idxn, an);

    float2* outp = reinterpret_cast<float2*>(out);
    float2* outn = reinterpret_cast<float2*>(out + (size_t)NN * DD);
    float2 pp = outp[node * 32 + lane];
    float2 pn = outn[node * 32 + lane];
    pp.x += ALPHA * ap.x;  pp.y += ALPHA * ap.y;
    pn.x += ALPHA * an.x;  pn.y += ALPHA * an.y;
    outp[node * 32 + lane] = pp;
    outn[node * 32 + lane] = pn;
}

extern "C" void kernel_launch(void* const* d_in, const int* in_sizes, int n_in,
                              void* d_out, int out_size) {
    const float* ue  = (const float*)d_in[0];
    const float* ie  = (const float*)d_in[1];
    const float* un  = (const float*)d_in[2];
    const float* inn = (const float*)d_in[3];
    const int* pe    = (const int*)d_in[4];
    const int* ne    = (const int*)d_in[5];
    float* out = (float*)d_out;

    const int* ps = pe;        const int* pd = pe + NE;
    const int* ns = ne;        const int* nd = ne + NE;

    k_zero<<<(NN + 255) / 256, 256>>>();
    k_hist<<<(NE / 2 + 255) / 256, 256>>>(pd, nd);
    {
        dim3 g1(NBLK_SCAN, 2);
        k_scan1<<<g1, SCAN_B>>>();
        k_scan2<<<2, 1024>>>();
        k_scan3<<<g1, SCAN_B>>>();
    }
    k_fill<<<(NE / 2 + 255) / 256, 256>>>(ps, pd, ns, nd);

    int conv_blocks = NN / 8;   // warp per node, 8 warps/block
    k_conv1<<<conv_blocks, 256>>>(ue, ie, un, inn, out);
    k_conv2<<<conv_blocks, 256>>>(out);
}